// round 8
// baseline (speedup 1.0000x reference)
#include <cuda_runtime.h>
#include <cstdint>

// Problem constants (fixed by the reference setup_inputs).
#define BROWS   1024
#define CCOLS   100000
#define C4      25000            // float4 per row
#define TOT4    (BROWS * C4)     // 25,600,000 float4 total
#define NTHR    256
#define G4      21760            // float4 per unit = 85 * 256 (< C4 -> <=2 rows)
#define NBLK    1184             // 148 SMs * 8 blocks, single full wave

#define SCALE   64.0f
#define MARGIN  0.35f
#define S_LOG2E 92.33248262743f  // 64 * log2(e)
#define LOG2E   1.4426950408889634f

// Scratch (device globals; no allocations allowed). Zero at load; every
// launch leaves them zeroed again so graph replays stay deterministic.
__device__ float        g_rowsum[BROWS];
__device__ unsigned int g_rc[BROWS];     // float4 contributions received
__device__ float        g_loss  = 0.0f;
__device__ unsigned int g_count = 0;

// Sum exp(S*x) over float4 indices [beg, end) with this block's threads.
__device__ __forceinline__ float seg_sum(const float4* __restrict__ xf4,
                                         int beg, int end, int tid) {
    float a0 = 0.0f, a1 = 0.0f, a2 = 0.0f, a3 = 0.0f;
#pragma unroll 8
    for (int idx = beg + tid; idx < end; idx += NTHR) {
        float4 v = __ldcs(&xf4[idx]);
        a0 += exp2f(v.x * S_LOG2E);
        a1 += exp2f(v.y * S_LOG2E);
        a2 += exp2f(v.z * S_LOG2E);
        a3 += exp2f(v.w * S_LOG2E);
    }
    return (a0 + a1) + (a2 + a3);
}

__device__ __forceinline__ float block_reduce(float v, int tid, float* smem) {
#pragma unroll
    for (int o = 16; o > 0; o >>= 1)
        v += __shfl_xor_sync(0xffffffffu, v, o);
    if ((tid & 31) == 0) smem[tid >> 5] = v;
    __syncthreads();
    float s = 0.0f;
    if (tid == 0) {
#pragma unroll
        for (int w = 0; w < NTHR / 32; ++w) s += smem[w];
    }
    __syncthreads();
    return s;  // valid on tid 0
}

// tid-0 only: publish a row partial; finalize the row if count completes.
__device__ __forceinline__ void publish_row(
    int row, float part, unsigned int cnt,
    const float* __restrict__ x, const int* __restrict__ label,
    float* __restrict__ out) {
    atomicAdd(&g_rowsum[row], part);
    __threadfence();
    unsigned int prev = atomicAdd(&g_rc[row], cnt);
    if (prev + cnt == (unsigned int)C4) {
        __threadfence();
        const float rsum = *(volatile float*)&g_rowsum[row];

        int lbl = label[row];
        if (lbl < 0) lbl = 0;
        if (lbl >= CCOLS) lbl = CCOLS - 1;
        const float xy = x[(size_t)row * CCOLS + lbl];

        const float numerator = SCALE * (xy - MARGIN);
        const float exp_num = exp2f(numerator * LOG2E);
        const float exp_sxy = exp2f(xy * S_LOG2E);
        const float denom = exp_num + (rsum - exp_sxy);
        const float L = (numerator - logf(denom)) * (1.0f / SCALE);

        g_rowsum[row] = 0.0f;   // reset row scratch for the next replay
        g_rc[row] = 0u;

        atomicAdd(&g_loss, L);
        __threadfence();
        unsigned int done = atomicAdd(&g_count, 1u);
        if (done == BROWS - 1) {
            float total = atomicAdd(&g_loss, 0.0f);
            out[0] = -total * (1.0f / (float)BROWS);
            g_loss = 0.0f;
            __threadfence();
            g_count = 0u;
        }
    }
}

__global__ __launch_bounds__(NTHR, 8) void loss_fused_kernel(
    const float* __restrict__ x,
    const int* __restrict__ label,
    float* __restrict__ out) {
    const int tid = threadIdx.x;
    const int start = blockIdx.x * G4;
    if (start >= TOT4) return;                 // trailing empty units
    const int end = min(start + G4, TOT4);

    const float4* __restrict__ xf4 = reinterpret_cast<const float4*>(x);

    // A unit spans at most two rows; split at the row boundary.
    const int rowA = start / C4;
    const int b4   = min(end, (rowA + 1) * C4);

    const float sumA = seg_sum(xf4, start, b4, tid);
    float sumB = 0.0f;
    const bool hasB = (b4 < end);
    if (hasB) sumB = seg_sum(xf4, b4, end, tid);

    __shared__ float smem[NTHR / 32];
    const float redA = block_reduce(sumA, tid, smem);
    float redB = 0.0f;
    if (hasB) redB = block_reduce(sumB, tid, smem);

    if (tid == 0) {
        publish_row(rowA, redA, (unsigned int)(b4 - start), x, label, out);
        if (hasB)
            publish_row(rowA + 1, redB, (unsigned int)(end - b4), x, label, out);
    }
}

extern "C" void kernel_launch(void* const* d_in, const int* in_sizes, int n_in,
                              void* d_out, int out_size) {
    const float* x = (const float*)d_in[0];
    const int* label = (const int*)d_in[1];
    float* out = (float*)d_out;

    loss_fused_kernel<<<NBLK, NTHR>>>(x, label, out);
}

// round 9
// speedup vs baseline: 1.1814x; 1.1814x over previous
#include <cuda_runtime.h>
#include <cstdint>

// Problem constants (fixed by the reference setup_inputs).
#define BROWS   1024
#define CCOLS   100000
#define HALF4   12500            // float4 per half-row
#define NTHR    128
#define MAIN_ITERS 97            // 97*128 = 12416 uniform float4
#define TAILN   (HALF4 - MAIN_ITERS * NTHR)   // 84 leftover float4
#define NBLK    (BROWS * 2)      // 2048 half-row blocks, all resident (1 wave)

#define SCALE   64.0f
#define MARGIN  0.35f
#define S_LOG2E 92.33248262743f  // 64 * log2(e)
#define LOG2E   1.4426950408889634f

// Scratch (device globals; no allocations allowed). Zero at load; every
// launch leaves them zeroed again so graph replays stay deterministic.
__device__ float        g_rowsum[BROWS];
__device__ unsigned int g_rc[BROWS];
__device__ float        g_loss  = 0.0f;
__device__ unsigned int g_count = 0;

__global__ __launch_bounds__(NTHR, 16) void loss_fused_kernel(
    const float* __restrict__ x,
    const int* __restrict__ label,
    float* __restrict__ out) {
    const int blk  = blockIdx.x;
    const int row  = blk >> 1;
    const int half = blk & 1;
    const int tid  = threadIdx.x;
    const float4* __restrict__ xr = reinterpret_cast<const float4*>(
        x + (size_t)row * CCOLS) + (size_t)half * HALF4;

    // ---- Stream this half-row: 97 uniform unroll-8 iters + 84 predicated.
    float acc0 = 0.0f, acc1 = 0.0f, acc2 = 0.0f, acc3 = 0.0f;
    int idx = tid;
#pragma unroll 8
    for (int k = 0; k < MAIN_ITERS; ++k) {
        float4 v = __ldcs(&xr[idx]);
        idx += NTHR;
        acc0 += exp2f(v.x * S_LOG2E);
        acc1 += exp2f(v.y * S_LOG2E);
        acc2 += exp2f(v.z * S_LOG2E);
        acc3 += exp2f(v.w * S_LOG2E);
    }
    if (tid < TAILN) {
        float4 v = __ldcs(&xr[idx]);
        acc0 += exp2f(v.x * S_LOG2E);
        acc1 += exp2f(v.y * S_LOG2E);
        acc2 += exp2f(v.z * S_LOG2E);
        acc3 += exp2f(v.w * S_LOG2E);
    }
    float acc = (acc0 + acc1) + (acc2 + acc3);

#pragma unroll
    for (int o = 16; o > 0; o >>= 1)
        acc += __shfl_xor_sync(0xffffffffu, acc, o);

    __shared__ float smem[NTHR / 32];
    if ((tid & 31) == 0) smem[tid >> 5] = acc;
    __syncthreads();

    if (tid == 0) {
        float part = 0.0f;
#pragma unroll
        for (int w = 0; w < NTHR / 32; ++w) part += smem[w];

        atomicAdd(&g_rowsum[row], part);
        __threadfence();
        unsigned int prev = atomicAdd(&g_rc[row], 1u);
        if (prev == 1u) {
            // Second arriver: finalize this row's loss term.
            __threadfence();
            const float rsum = *(volatile float*)&g_rowsum[row];

            int lbl = label[row];
            if (lbl < 0) lbl = 0;
            if (lbl >= CCOLS) lbl = CCOLS - 1;
            const float xy = x[(size_t)row * CCOLS + lbl];

            const float numerator = SCALE * (xy - MARGIN);
            const float exp_num = exp2f(numerator * LOG2E);
            const float exp_sxy = exp2f(xy * S_LOG2E);
            const float denom = exp_num + (rsum - exp_sxy);
            const float L = (numerator - logf(denom)) * (1.0f / SCALE);

            g_rowsum[row] = 0.0f;   // reset row scratch for the next replay
            g_rc[row] = 0u;

            atomicAdd(&g_loss, L);
            __threadfence();
            unsigned int done = atomicAdd(&g_count, 1u);
            if (done == BROWS - 1) {
                float total = atomicAdd(&g_loss, 0.0f);
                out[0] = -total * (1.0f / (float)BROWS);
                g_loss = 0.0f;
                __threadfence();
                g_count = 0u;
            }
        }
    }
}

extern "C" void kernel_launch(void* const* d_in, const int* in_sizes, int n_in,
                              void* d_out, int out_size) {
    const float* x = (const float*)d_in[0];
    const int* label = (const int*)d_in[1];
    float* out = (float*)d_out;

    loss_fused_kernel<<<NBLK, NTHR>>>(x, label, out);
}

// round 10
// speedup vs baseline: 1.2661x; 1.0716x over previous
#include <cuda_runtime.h>
#include <cstdint>

// Problem constants (fixed by the reference setup_inputs).
#define BROWS 1024
#define CCOLS 100000
#define C4    (CCOLS / 4)        // 25000 float4 per row
#define NTHR  256
#define MAIN_ITERS 96            // uniform, bounds-check-free iterations
// tail: idx in [tid + 96*256, 25000) handled by a short checked loop

#define SCALE   64.0f
#define MARGIN  0.35f
#define S_LOG2E 92.33248262743f  // 64 * log2(e)
#define LOG2E   1.4426950408889634f

// Scratch (device globals: no allocations allowed). Zero at load; the last
// block resets them each launch so graph replays stay correct.
__device__ float g_loss = 0.0f;
__device__ unsigned int g_count = 0;

// min-blocks 7 (grid provides only 6.92/SM anyway) -> ptxas budget 36 regs,
// letting more LDG.128 results stay buffered (deeper effective MLP).
__global__ __launch_bounds__(NTHR, 7) void loss_fused_kernel(
    const float* __restrict__ x,
    const int* __restrict__ label,
    float* __restrict__ out) {
    const int row = blockIdx.x;
    const int tid = threadIdx.x;
    const float4* __restrict__ xr =
        reinterpret_cast<const float4*>(x + (size_t)row * CCOLS);

    // Early gather of the target logit; consumed only at the very end.
    float xy = 0.0f;
    if (tid == 0) {
        int lbl = label[row];
        if (lbl < 0) lbl = 0;
        if (lbl >= CCOLS) lbl = CCOLS - 1;
        xy = x[(size_t)row * CCOLS + lbl];
    }

    // ---- Main stream: 96 uniform iterations, unroll 8, no bounds checks.
    float acc0 = 0.0f, acc1 = 0.0f, acc2 = 0.0f, acc3 = 0.0f;
    int idx = tid;
#pragma unroll 8
    for (int k = 0; k < MAIN_ITERS; ++k) {
        float4 v = __ldcs(&xr[idx]);
        idx += NTHR;
        acc0 += exp2f(v.x * S_LOG2E);
        acc1 += exp2f(v.y * S_LOG2E);
        acc2 += exp2f(v.z * S_LOG2E);
        acc3 += exp2f(v.w * S_LOG2E);
    }
    // Tail: remaining 424 float4.
    for (; idx < C4; idx += NTHR) {
        float4 v = __ldcs(&xr[idx]);
        acc0 += exp2f(v.x * S_LOG2E);
        acc1 += exp2f(v.y * S_LOG2E);
        acc2 += exp2f(v.z * S_LOG2E);
        acc3 += exp2f(v.w * S_LOG2E);
    }
    float acc = (acc0 + acc1) + (acc2 + acc3);

#pragma unroll
    for (int o = 16; o > 0; o >>= 1)
        acc += __shfl_xor_sync(0xffffffffu, acc, o);

    __shared__ float smem[NTHR / 32];
    if ((tid & 31) == 0) smem[tid >> 5] = acc;
    __syncthreads();

    if (tid == 0) {
        float rsum = 0.0f;
#pragma unroll
        for (int w = 0; w < NTHR / 32; ++w) rsum += smem[w];

        // This block's complete loss term.
        const float numerator = SCALE * (xy - MARGIN);
        const float exp_num = exp2f(numerator * LOG2E);
        const float exp_sxy = exp2f(xy * S_LOG2E);
        const float denom = exp_num + (rsum - exp_sxy);
        const float L = (numerator - logf(denom)) * (1.0f / SCALE);

        atomicAdd(&g_loss, L);
        __threadfence();  // order g_loss update before the counter signal
        unsigned int prev = atomicAdd(&g_count, 1u);
        if (prev == BROWS - 1) {
            float total = atomicAdd(&g_loss, 0.0f);
            out[0] = -total * (1.0f / (float)BROWS);
            g_loss = 0.0f;
            __threadfence();
            g_count = 0;
        }
    }
}

extern "C" void kernel_launch(void* const* d_in, const int* in_sizes, int n_in,
                              void* d_out, int out_size) {
    const float* x = (const float*)d_in[0];
    const int* label = (const int*)d_in[1];
    float* out = (float*)d_out;

    loss_fused_kernel<<<BROWS, NTHR>>>(x, label, out);
}